// round 2
// baseline (speedup 1.0000x reference)
#include <cuda_runtime.h>
#include <cuda_bf16.h>

#define NB 128
#define NT 256
#define EMBED 1024
#define WIN 64
#define NK (2*WIN+1)   // 129
#define GW 256         // matrix W dimension

// Scratch (device globals: no allocation allowed)
__device__ float g_q[EMBED];
__device__ float g_wpart[16][EMBED];
__device__ float g_w[EMBED];
__device__ float g_s[NK];
__device__ float g_abar[EMBED];
__device__ float g_o[EMBED];
// Grid barrier state: monotonic counters -> safe across graph replays, no reset needed.
__device__ unsigned g_arrive = 0;
__device__ unsigned g_rel = 0;

__device__ __forceinline__ void grid_sync() {
    __threadfence();            // publish this thread's stores before arriving
    __syncthreads();            // all threads in block done
    if (threadIdx.x == 0) {
        unsigned a = atomicAdd(&g_arrive, 1u) + 1u;
        unsigned target = (a + NB - 1u) / NB;   // episode index this block must wait for
        if ((a % NB) == 0u) {
            atomicAdd(&g_rel, 1u);              // last arriver releases the episode
        } else {
            while (atomicAdd(&g_rel, 0u) < target) { __nanosleep(32); }
        }
    }
    __syncthreads();
}

__device__ __forceinline__ float warp_reduce(float v) {
    #pragma unroll
    for (int o = 16; o; o >>= 1) v += __shfl_xor_sync(0xffffffffu, v, o);
    return v;
}

// out[row] = dot(W[row,:], x) + b[row]; warp-per-row, 8 rows per block.
template <bool LDCG_X>
__device__ __forceinline__ void gemv_rows(const float* __restrict__ W,
                                          const float4* __restrict__ x4,
                                          const float* __restrict__ b,
                                          float* __restrict__ out) {
    int wid = threadIdx.x >> 5, lane = threadIdx.x & 31;
    int row = blockIdx.x * 8 + wid;
    const float4* Wrow = (const float4*)(W + (size_t)row * EMBED);
    float acc = 0.f;
    #pragma unroll
    for (int i = 0; i < 8; i++) {
        float4 wv = Wrow[i * 32 + lane];
        float4 xv = LDCG_X ? __ldcg(&x4[i * 32 + lane]) : x4[i * 32 + lane];
        acc += wv.x * xv.x + wv.y * xv.y + wv.z * xv.z + wv.w * xv.w;
    }
    acc = warp_reduce(acc);
    if (lane == 0) out[row] = acc + b[row];
}

__global__ void __launch_bounds__(NT, 1)
fused_local_attn(const float* __restrict__ matrix,
                 const float* __restrict__ Wq, const float* __restrict__ bq,
                 const float* __restrict__ Wk,
                 const float* __restrict__ Wv, const float* __restrict__ bv,
                 const float* __restrict__ Wo, const float* __restrict__ bo,
                 const int* __restrict__ ppx, const int* __restrict__ ppy,
                 float* __restrict__ out)
{
    const int tid  = threadIdx.x;
    const int bid  = blockIdx.x;
    const int wid  = tid >> 5;
    const int lane = tid & 31;

    __shared__ __align__(16) float sh[1184];

    const int px = ppx[0], py = ppy[0];
    const int hq = 2 * px - WIN;                 // global h of attention row r=px
    const int wq = 2 * py - WIN;                 // global w of the query token q=py
    const float* rowbase = matrix + (size_t)hq * GW * EMBED;
    const float* xvec = rowbase + (size_t)wq * EMBED;            // query input token
    const float* keys = rowbase + (size_t)(py - WIN) * EMBED;    // a_k = keys + k*EMBED

    // ---- Phase A: q = Wq @ x + bq --------------------------------------
    gemv_rows<false>(Wq, (const float4*)xvec, bq, g_q);
    grid_sync();

    // ---- Phase B: partials of w = Wk^T @ q (row-wise reads of Wk) -------
    {
        int et = bid & 7;        // e-tile: e in [et*128, et*128+128)
        int fc = bid >> 3;       // f-chunk: f in [fc*64, fc*64+64)
        float4 acc = make_float4(0.f, 0.f, 0.f, 0.f);
        int f0 = fc * 64 + wid;
        #pragma unroll
        for (int i = 0; i < 8; i++) {
            int f = f0 + i * 8;
            float qf = __ldcg(&g_q[f]);
            float4 wv = ((const float4*)Wk)[(size_t)f * (EMBED / 4) + et * 32 + lane];
            acc.x += qf * wv.x; acc.y += qf * wv.y; acc.z += qf * wv.z; acc.w += qf * wv.w;
        }
        float4* shB = (float4*)sh;
        shB[wid * 32 + lane] = acc;
        __syncthreads();
        if (wid == 0) {
            float4 s4 = shB[lane];
            #pragma unroll
            for (int j = 1; j < 8; j++) {
                float4 t4 = shB[j * 32 + lane];
                s4.x += t4.x; s4.y += t4.y; s4.z += t4.z; s4.w += t4.w;
            }
            ((float4*)&g_wpart[fc][et * 128])[lane] = s4;
        }
    }
    grid_sync();

    // ---- Phase B2: w[e] = sum_fc wpart[fc][e]  (block owns 8 e's) -------
    {
        if (tid < 128) {
            int el = tid >> 4, fc = tid & 15;
            sh[tid] = __ldcg(&g_wpart[fc][bid * 8 + el]);   // sh[el*16+fc] == sh[tid]
        }
        __syncthreads();
        if (tid < 8) {
            float s = 0.f;
            #pragma unroll
            for (int j = 0; j < 16; j++) s += sh[tid * 16 + j];
            g_w[bid * 8 + tid] = s;
        }
    }
    grid_sync();

    // ---- Phase C: s[k] = dot(w, a_k)  (block per k; block 0 also k=128) -
    for (int k = bid; k < NK; k += NB) {
        const float4* a4 = (const float4*)(keys + (size_t)k * EMBED);
        float4 wv = __ldcg(&((const float4*)g_w)[tid]);
        float4 av = a4[tid];
        float p = wv.x * av.x + wv.y * av.y + wv.z * av.z + wv.w * av.w;
        p = warp_reduce(p);
        if (lane == 0) sh[wid] = p;
        __syncthreads();
        if (tid == 0) {
            float s = 0.f;
            #pragma unroll
            for (int j = 0; j < 8; j++) s += sh[j];
            g_s[k] = s;
        }
        __syncthreads();
    }
    grid_sync();

    // ---- Phase D: softmax + abar[e] = sum_k p[k] * a_k[e] ---------------
    {
        float* s_sh = sh;            // [0,129)
        float* p_sh = sh + 132;      // [132,261)
        float* red  = sh + 272;      // [272,528)
        if (tid < NK) s_sh[tid] = __ldcg(&g_s[tid]);
        __syncthreads();
        const float scale = 0.03125f;   // 1/sqrt(1024)
        if (wid == 0) {
            float m = -1e30f;
            for (int k = lane; k < NK; k += 32) m = fmaxf(m, s_sh[k]);
            #pragma unroll
            for (int o = 16; o; o >>= 1) m = fmaxf(m, __shfl_xor_sync(0xffffffffu, m, o));
            float z = 0.f;
            for (int k = lane; k < NK; k += 32) {
                float e = __expf((s_sh[k] - m) * scale);
                p_sh[k] = e;
                z += e;
            }
            z = warp_reduce(z);
            if (lane == 0) sh[264] = 1.f / z;
        }
        __syncthreads();
        float zinv = sh[264];
        int kpart = tid >> 3, eidx = tid & 7;
        int e = bid * 8 + eidx;
        float acc = 0.f;
        for (int k = kpart; k < NK; k += 32)
            acc += p_sh[k] * __ldcg(&keys[(size_t)k * EMBED + e]);
        red[tid] = acc;              // layout: kpart*8 + eidx
        __syncthreads();
        if (tid < 8) {
            float s = 0.f;
            #pragma unroll
            for (int j = 0; j < 32; j++) s += red[j * 8 + tid];
            g_abar[bid * 8 + tid] = s * zinv;
        }
    }
    grid_sync();

    // ---- Phase E: o = Wv @ abar + bv ------------------------------------
    gemv_rows<true>(Wv, (const float4*)g_abar, bv, g_o);
    grid_sync();

    // ---- Phase F: out = Wo @ o + bo -------------------------------------
    gemv_rows<true>(Wo, (const float4*)g_o, bo, out);
}

extern "C" void kernel_launch(void* const* d_in, const int* in_sizes, int n_in,
                              void* d_out, int out_size) {
    const float* matrix = (const float*)d_in[0];
    const float* Wq = (const float*)d_in[1];
    const float* bq = (const float*)d_in[2];
    const float* Wk = (const float*)d_in[3];
    // d_in[4] = bk: mathematically eliminated (constant shift under softmax)
    const float* Wv = (const float*)d_in[5];
    const float* bv = (const float*)d_in[6];
    const float* Wo = (const float*)d_in[7];
    const float* bo = (const float*)d_in[8];
    const int* px = (const int*)d_in[9];
    const int* py = (const int*)d_in[10];

    fused_local_attn<<<NB, NT>>>(matrix, Wq, bq, Wk, Wv, bv, Wo, bo, px, py,
                                 (float*)d_out);
}

// round 5
// speedup vs baseline: 1.2159x; 1.2159x over previous
#include <cuda_runtime.h>
#include <cuda_bf16.h>

#define NB 128
#define NT 512
#define EMBED 1024
#define WIN 64
#define NK (2*WIN+1)   // 129
#define GW 256         // matrix W dimension

// Scratch (device globals: no allocation allowed)
__device__ float g_q[EMBED];
__device__ float g_wpart[4][EMBED];
__device__ float g_s[NK];
__device__ float g_abar[EMBED];
__device__ float g_o[EMBED];
// Grid barrier state: monotonic counters -> safe across graph replays, no reset.
// EXACT implementation from the only passing run (R1): atomic release + atomic
// poll with nanosleep backoff.
__device__ unsigned g_arrive = 0;
__device__ unsigned g_rel = 0;

__device__ __forceinline__ void grid_sync() {
    __threadfence();            // publish this thread's stores before arriving
    __syncthreads();            // all threads in block done
    if (threadIdx.x == 0) {
        unsigned a = atomicAdd(&g_arrive, 1u) + 1u;
        unsigned target = (a + NB - 1u) / NB;   // episode index this block must wait for
        if ((a % NB) == 0u) {
            atomicAdd(&g_rel, 1u);              // last arriver releases the episode
        } else {
            while (atomicAdd(&g_rel, 0u) < target) { __nanosleep(32); }
        }
    }
    __syncthreads();
}

__device__ __forceinline__ float warp_reduce(float v) {
    #pragma unroll
    for (int o = 16; o; o >>= 1) v += __shfl_xor_sync(0xffffffffu, v, o);
    return v;
}

__device__ __forceinline__ float dot4(float4 a, float4 b) {
    return a.x * b.x + a.y * b.y + a.z * b.z + a.w * b.w;
}

// Shared memory regions (floats)
//  R0 [0,1024)      : x / q / w staging (256 float4)
//  R1 [1024,3072)   : big reduction buffer (512 float4 or 512 floats)
//  R2 [3072,3328)   : second-stage reduction (64 float4)
//  R3 [3328,3457)   : s_sh
//  R4 [3472,3601)   : p_sh
//  R5 [3616,3712)   : misc (warp accs, zinv)
#define SM_TOTAL 3712

__global__ void __launch_bounds__(NT, 1)
fused_local_attn(const float* __restrict__ matrix,
                 const float* __restrict__ Wq, const float* __restrict__ bq,
                 const float* __restrict__ Wk,
                 const float* __restrict__ Wv, const float* __restrict__ bv,
                 const float* __restrict__ Wo, const float* __restrict__ bo,
                 const int* __restrict__ ppx, const int* __restrict__ ppy,
                 float* __restrict__ out)
{
    const int tid  = threadIdx.x;
    const int bid  = blockIdx.x;
    const int wid  = tid >> 5;
    const int lane = tid & 31;

    __shared__ __align__(16) float sm[SM_TOTAL];
    float4* R0_4 = (float4*)sm;                 // 256 float4
    float4* R1_4 = (float4*)(sm + 1024);        // 512 float4
    float4* R2_4 = (float4*)(sm + 3072);        // 64 float4
    float*  R1   = sm + 1024;
    float*  s_sh = sm + 3328;
    float*  p_sh = sm + 3472;
    float*  misc = sm + 3616;

    const int px = ppx[0], py = ppy[0];
    const int hq = 2 * px - WIN;
    const int wq = 2 * py - WIN;
    const float* rowbase = matrix + (size_t)hq * GW * EMBED;
    const float4* xvec4 = (const float4*)(rowbase + (size_t)wq * EMBED);
    const float*  keys  = rowbase + (size_t)(py - WIN) * EMBED;
    const float4* keys4 = (const float4*)keys;

    // =========== Phase A: q = Wq @ x + bq (8 rows/block, 2 warps/row) ====
    {
        if (tid < 256) R0_4[tid] = xvec4[tid];
        __syncthreads();
        int row = bid * 8 + (wid >> 1);
        int half = wid & 1;
        const float4* Wrow = (const float4*)(Wq + (size_t)row * EMBED);
        float4 w0 = Wrow[half * 128 + 0 * 32 + lane];
        float4 w1 = Wrow[half * 128 + 1 * 32 + lane];
        float4 w2 = Wrow[half * 128 + 2 * 32 + lane];
        float4 w3 = Wrow[half * 128 + 3 * 32 + lane];
        float acc = dot4(w0, R0_4[half * 128 + 0 * 32 + lane])
                  + dot4(w1, R0_4[half * 128 + 1 * 32 + lane])
                  + dot4(w2, R0_4[half * 128 + 2 * 32 + lane])
                  + dot4(w3, R0_4[half * 128 + 3 * 32 + lane]);
        acc = warp_reduce(acc);
        if (lane == 0) misc[wid] = acc;
        __syncthreads();
        if (tid < 8) g_q[bid * 8 + tid] = misc[2 * tid] + misc[2 * tid + 1] + bq[bid * 8 + tid];
    }
    grid_sync();

    // =========== Phase B: w-partials.  block = (fc, et): fc=bid>>5 (4 f-chunks
    // of 256), et=bid&31 (32 e's).  w[e] = sum_f q[f]*Wk[f][e]. ===========
    {
        int fc = bid >> 5, et = bid & 31;
        int f0 = fc * 256;
        if (tid < 64) R0_4[tid] = __ldcg(&((const float4*)g_q)[f0 / 4 + tid]);
        __syncthreads();
        const float* sq = sm;
        int v = tid & 7;                         // float4 column within 32-e tile
        float4 acc = make_float4(0.f, 0.f, 0.f, 0.f);
        #pragma unroll
        for (int i = 0; i < 4; i++) {
            int fl = i * 64 + (tid >> 3);
            float qf = sq[fl];
            float4 wv = ((const float4*)Wk)[(size_t)(f0 + fl) * 256 + et * 8 + v];
            acc.x += qf * wv.x; acc.y += qf * wv.y; acc.z += qf * wv.z; acc.w += qf * wv.w;
        }
        R1_4[tid] = acc;
        __syncthreads();
        if (tid < 64) {                           // stage 1: 512 -> 64
            int vv = tid & 7, g = tid >> 3;
            float4 s = make_float4(0.f, 0.f, 0.f, 0.f);
            #pragma unroll
            for (int j = 0; j < 8; j++) {
                float4 t4 = R1_4[vv + 8 * (g * 8 + j)];
                s.x += t4.x; s.y += t4.y; s.z += t4.z; s.w += t4.w;
            }
            R2_4[tid] = s;
        }
        __syncthreads();
        if (tid < 8) {                            // stage 2: 64 -> 8 float4
            float4 s = make_float4(0.f, 0.f, 0.f, 0.f);
            #pragma unroll
            for (int g = 0; g < 8; g++) {
                float4 t4 = R2_4[tid + 8 * g];
                s.x += t4.x; s.y += t4.y; s.z += t4.z; s.w += t4.w;
            }
            ((float4*)g_wpart[fc])[et * 8 + tid] = s;
        }
    }
    grid_sync();

    // ===== Phase C: reduce w-partials (prologue) + s[k] = w . a_k ========
    {
        if (tid < 256) {                          // w into R0 (4 coalesced L2 reads)
            float4 s = __ldcg(&((const float4*)g_wpart[0])[tid]);
            #pragma unroll
            for (int fc = 1; fc < 4; fc++) {
                float4 t4 = __ldcg(&((const float4*)g_wpart[fc])[tid]);
                s.x += t4.x; s.y += t4.y; s.z += t4.z; s.w += t4.w;
            }
            R0_4[tid] = s;
        }
        __syncthreads();
        for (int k = bid; k < NK; k += NB) {      // block 0 also does k=128
            float p = 0.f;
            if (tid < 256) p = dot4(R0_4[tid], keys4[k * 256 + tid]);
            p = warp_reduce(p);
            if (lane == 0 && wid < 8) misc[wid] = p;
            __syncthreads();
            if (tid == 0) {
                float s = 0.f;
                #pragma unroll
                for (int j = 0; j < 8; j++) s += misc[j];
                g_s[k] = s;
            }
            __syncthreads();
        }
    }
    grid_sync();

    // ===== Phase D: softmax + abar[e] = sum_k p[k]*a_k[e] (8 e's/block) ==
    {
        if (tid < NK) s_sh[tid] = __ldcg(&g_s[tid]);
        __syncthreads();
        const float scale = 0.03125f;             // 1/sqrt(1024)
        if (wid == 0) {
            float m = -1e30f;
            for (int k = lane; k < NK; k += 32) m = fmaxf(m, s_sh[k]);
            #pragma unroll
            for (int o = 16; o; o >>= 1) m = fmaxf(m, __shfl_xor_sync(0xffffffffu, m, o));
            float z = 0.f;
            for (int k = lane; k < NK; k += 32) {
                float e = __expf((s_sh[k] - m) * scale);
                p_sh[k] = e;
                z += e;
            }
            z = warp_reduce(z);
            if (lane == 0) misc[16] = 1.f / z;
        }
        __syncthreads();
        float zinv = misc[16];
        int eidx = tid & 7, kpart = tid >> 3;     // 64 k-partitions
        int e = bid * 8 + eidx;
        float acc = 0.f;
        for (int k = kpart; k < NK; k += 64)
            acc += p_sh[k] * __ldcg(&keys[(size_t)k * EMBED + e]);
        R1[tid] = acc;
        __syncthreads();
        if (tid < 64) {                           // 512 -> 64
            int vv = tid & 7, g = tid >> 3;
            float s = 0.f;
            #pragma unroll
            for (int j = 0; j < 8; j++) s += R1[vv + 8 * (g * 8 + j)];
            sm[3072 + tid] = s;                   // reuse R2 as scalar
        }
        __syncthreads();
        if (tid < 8) {                            // 64 -> 8
            float s = 0.f;
            #pragma unroll
            for (int g = 0; g < 8; g++) s += sm[3072 + tid + 8 * g];
            g_abar[bid * 8 + tid] = s * zinv;
        }
    }
    grid_sync();

    // =========== Phase E: o = Wv @ abar + bv =============================
    {
        if (tid < 256) R0_4[tid] = __ldcg(&((const float4*)g_abar)[tid]);
        __syncthreads();
        int row = bid * 8 + (wid >> 1);
        int half = wid & 1;
        const float4* Wrow = (const float4*)(Wv + (size_t)row * EMBED);
        float4 w0 = Wrow[half * 128 + 0 * 32 + lane];
        float4 w1 = Wrow[half * 128 + 1 * 32 + lane];
        float4 w2 = Wrow[half * 128 + 2 * 32 + lane];
        float4 w3 = Wrow[half * 128 + 3 * 32 + lane];
        float acc = dot4(w0, R0_4[half * 128 + 0 * 32 + lane])
                  + dot4(w1, R0_4[half * 128 + 1 * 32 + lane])
                  + dot4(w2, R0_4[half * 128 + 2 * 32 + lane])
                  + dot4(w3, R0_4[half * 128 + 3 * 32 + lane]);
        acc = warp_reduce(acc);
        if (lane == 0) misc[wid] = acc;
        __syncthreads();
        if (tid < 8) g_o[bid * 8 + tid] = misc[2 * tid] + misc[2 * tid + 1] + bv[bid * 8 + tid];
    }
    grid_sync();

    // =========== Phase F: out = Wo @ o + bo ==============================
    {
        if (tid < 256) R0_4[tid] = __ldcg(&((const float4*)g_o)[tid]);
        __syncthreads();
        int row = bid * 8 + (wid >> 1);
        int half = wid & 1;
        const float4* Wrow = (const float4*)(Wo + (size_t)row * EMBED);
        float4 w0 = Wrow[half * 128 + 0 * 32 + lane];
        float4 w1 = Wrow[half * 128 + 1 * 32 + lane];
        float4 w2 = Wrow[half * 128 + 2 * 32 + lane];
        float4 w3 = Wrow[half * 128 + 3 * 32 + lane];
        float acc = dot4(w0, R0_4[half * 128 + 0 * 32 + lane])
                  + dot4(w1, R0_4[half * 128 + 1 * 32 + lane])
                  + dot4(w2, R0_4[half * 128 + 2 * 32 + lane])
                  + dot4(w3, R0_4[half * 128 + 3 * 32 + lane]);
        acc = warp_reduce(acc);
        if (lane == 0) misc[wid] = acc;
        __syncthreads();
        if (tid < 8) out[bid * 8 + tid] = misc[2 * tid] + misc[2 * tid + 1] + bo[bid * 8 + tid];
    }
}

extern "C" void kernel_launch(void* const* d_in, const int* in_sizes, int n_in,
                              void* d_out, int out_size) {
    const float* matrix = (const float*)d_in[0];
    const float* Wq = (const float*)d_in[1];
    const float* bq = (const float*)d_in[2];
    const float* Wk = (const float*)d_in[3];
    // d_in[4] = bk: mathematically eliminated (constant shift under softmax)
    const float* Wv = (const float*)d_in[5];
    const float* bv = (const float*)d_in[6];
    const float* Wo = (const float*)d_in[7];
    const float* bo = (const float*)d_in[8];
    const int* px = (const int*)d_in[9];
    const int* py = (const int*)d_in[10];

    fused_local_attn<<<NB, NT>>>(matrix, Wq, bq, Wk, Wv, bv, Wo, bo, px, py,
                                 (float*)d_out);
}